// round 3
// baseline (speedup 1.0000x reference)
#include <cuda_runtime.h>
#include <cuda_bf16.h>

#define NFEAT 17
#define NEV 16
#define PPE 65536
#define NPTS (NEV * PPE)
#define MAXCOND 4096
#define T_B 0.2f
#define R2 0.49f
#define CAP 10240          // smem candidate capacity (20 B/entry -> 200 KB)

// Scratch (device globals — no allocation allowed)
__device__ float4 g_pts[NPTS];      // (c0, c1, c2, beta) packed
__device__ float  g_beta[NPTS];     // contiguous betas for the initial scan
__device__ int    g_cidx[NEV * MAXCOND];
__device__ int    g_ccnt[NEV];

// ---------------------------------------------------------------------------
// 1) Fused zero-fill + pack.
// ---------------------------------------------------------------------------
__global__ void zero_pack_kernel(const float* __restrict__ x,
                                 float* __restrict__ out, long long n) {
    const long long gid    = (long long)blockIdx.x * blockDim.x + threadIdx.x;
    const long long stride = (long long)gridDim.x * blockDim.x;

    const long long n4 = n >> 2;
    float4 z; z.x = 0.f; z.y = 0.f; z.z = 0.f; z.w = 0.f;
    for (long long j = gid; j < n4; j += stride)
        reinterpret_cast<float4*>(out)[j] = z;
    if (gid < (n & 3)) out[(n4 << 2) + gid] = 0.f;

    if (gid < NPTS) {
        const float* r = x + gid * NFEAT;
        float4 p;
        p.x = r[14];
        p.y = r[15];
        p.z = r[16];
        p.w = r[9];
        g_pts[gid]  = p;
        g_beta[gid] = p.w;
    }
}

// ---------------------------------------------------------------------------
// (b, i) argmax across 1024 threads, min-index tie-break (matches jnp.argmax).
// ---------------------------------------------------------------------------
__device__ __forceinline__ void block_argmax(float& b, int& i,
                                             float* swb, int* swi, int t) {
    #pragma unroll
    for (int off = 16; off > 0; off >>= 1) {
        float ob = __shfl_down_sync(0xFFFFFFFFu, b, off);
        int   oi = __shfl_down_sync(0xFFFFFFFFu, i, off);
        if (ob > b || (ob == b && oi < i)) { b = ob; i = oi; }
    }
    const int warp = t >> 5, lane = t & 31;
    if (lane == 0) { swb[warp] = b; swi[warp] = i; }
    __syncthreads();
    if (warp == 0) {
        b = swb[lane]; i = swi[lane];
        #pragma unroll
        for (int off = 16; off > 0; off >>= 1) {
            float ob = __shfl_down_sync(0xFFFFFFFFu, b, off);
            int   oi = __shfl_down_sync(0xFFFFFFFFu, i, off);
            if (ob > b || (ob == b && oi < i)) { b = ob; i = oi; }
        }
        if (lane == 0) { swb[0] = b; swi[0] = i; }
    }
    __syncthreads();
    b = swb[0]; i = swi[0];
}

// ---------------------------------------------------------------------------
// 2) Greedy condensation: dense phase over a 64-bit candidate mask per thread
//    (candidates = unassigned & beta >= T_B; low-beta points never affect the
//    output), then compact survivors into shared memory and finish there.
// ---------------------------------------------------------------------------
__global__ void __launch_bounds__(1024, 1) condense_kernel() {
    extern __shared__ char dyn[];
    float* sx   = (float*)dyn;
    float* sy   = sx + CAP;
    float* sz   = sy + CAP;
    float* sb   = sz + CAP;
    int*   sidx = (int*)(sb + CAP);

    __shared__ float swb[32];
    __shared__ int   swi[32];
    __shared__ int   scnt[32];
    __shared__ int   s_total;
    __shared__ int   s_wr;

    const int e = blockIdx.x;
    const int t = threadIdx.x;
    const float4* __restrict__ pts  = g_pts  + e * PPE;
    const float*  __restrict__ beta = g_beta + e * PPE;

    // ---- initial scan: build candidate mask + argmax (coalesced) ----
    unsigned long long cand = 0ULL;
    float best = -1.0f;
    int   bidx = 0x7FFFFFFF;
    #pragma unroll
    for (int k = 0; k < 64; ++k) {
        const int i = t + (k << 10);
        const float b = beta[i];
        if (b >= T_B) {
            cand |= (1ULL << k);
            if (b > best) { best = b; bidx = i; }   // ascending i: '>' keeps first
        }
    }
    block_argmax(best, bidx, swb, swi, t);

    int count = 0;

    // ---- dense phase ----
    while (best >= T_B) {
        const int ref = bidx;
        if (t == 0) g_cidx[e * MAXCOND + count] = ref;
        ++count;

        const float4 rc = __ldg(&pts[ref]);   // broadcast load
        const float cx = rc.x, cy = rc.y, cz = rc.z;

        best = -1.0f; bidx = 0x7FFFFFFF;
        #pragma unroll
        for (int k = 0; k < 64; ++k) {
            if (cand & (1ULL << k)) {
                const int i = t + (k << 10);
                const float4 p = pts[i];
                const float dx = p.x - cx;
                const float dy = p.y - cy;
                const float dz = p.z - cz;
                const float d2 = dx * dx + dy * dy + dz * dz;
                if (d2 <= R2) cand &= ~(1ULL << k);
                else if (p.w > best) { best = p.w; bidx = i; }
            }
        }

        // survivor count reduction
        int c = __popcll(cand);
        #pragma unroll
        for (int off = 16; off > 0; off >>= 1)
            c += __shfl_down_sync(0xFFFFFFFFu, c, off);
        if ((t & 31) == 0) scnt[t >> 5] = c;

        block_argmax(best, bidx, swb, swi, t);  // syncthreads inside covers scnt

        if (t == 0) {
            int tot = 0;
            #pragma unroll
            for (int w = 0; w < 32; ++w) tot += scnt[w];
            s_total = tot;
        }
        __syncthreads();
        if (s_total <= CAP) break;
    }

    // ---- compact surviving candidates into shared memory ----
    if (t == 0) s_wr = 0;
    __syncthreads();
    {
        unsigned long long m = cand;
        while (m) {
            const int k = __ffsll((long long)m) - 1;
            m &= m - 1;
            const int i = t + (k << 10);
            const float4 p = pts[i];
            const int pos = atomicAdd(&s_wr, 1);
            sx[pos] = p.x; sy[pos] = p.y; sz[pos] = p.z;
            sb[pos] = p.w; sidx[pos] = i;
        }
    }
    __syncthreads();
    const int S = s_wr;

    // ---- sparse phase: everything in smem ----
    while (best >= T_B) {
        const int ref = bidx;
        if (t == 0) g_cidx[e * MAXCOND + count] = ref;
        ++count;

        const float4 rc = __ldg(&pts[ref]);
        const float cx = rc.x, cy = rc.y, cz = rc.z;

        best = -1.0f; bidx = 0x7FFFFFFF;
        for (int j = t; j < S; j += 1024) {
            const float b = sb[j];
            if (b < 0.0f) continue;               // suppressed
            const float dx = sx[j] - cx;
            const float dy = sy[j] - cy;
            const float dz = sz[j] - cz;
            const float d2 = dx * dx + dy * dy + dz * dz;
            if (d2 <= R2) {
                sb[j] = -1.0f;
            } else {
                const int i = sidx[j];
                if (b > best || (b == best && i < bidx)) { best = b; bidx = i; }
            }
        }
        block_argmax(best, bidx, swb, swi, t);
    }

    if (t == 0) g_ccnt[e] = count;
}

// ---------------------------------------------------------------------------
// 3) Scatter condensate rows + row splits (fused).
// ---------------------------------------------------------------------------
__global__ void scatter_splits_kernel(const float* __restrict__ x,
                                      float* __restrict__ out,
                                      long long splits_off, int do_splits) {
    const int e    = blockIdx.x;
    const int cnt  = g_ccnt[e];
    const int warp = threadIdx.x >> 5;
    const int lane = threadIdx.x & 31;
    const int nw   = blockDim.x >> 5;
    for (int c = warp; c < cnt; c += nw) {
        const long long row = (long long)e * PPE + g_cidx[e * MAXCOND + c];
        if (lane < NFEAT)
            out[row * NFEAT + lane] = x[row * NFEAT + lane];
    }
    if (e == 0 && threadIdx.x == 0 && do_splits) {
        int acc = 0;
        out[splits_off] = 0.0f;
        #pragma unroll
        for (int ev = 0; ev < NEV; ++ev) {
            acc += g_ccnt[ev];
            out[splits_off + 1 + ev] = (float)acc;
        }
    }
}

// ---------------------------------------------------------------------------
extern "C" void kernel_launch(void* const* d_in, const int* in_sizes, int n_in,
                              void* d_out, int out_size) {
    const float* x   = (const float*)d_in[0];
    float*       out = (float*)d_out;
    const long long n = (long long)out_size;

    // opt-in to 200 KB dynamic smem for condense (idempotent; host-side attr)
    static const size_t dyn_smem = (size_t)CAP * 20;
    cudaFuncSetAttribute(condense_kernel,
                         cudaFuncAttributeMaxDynamicSharedMemorySize,
                         (int)dyn_smem);

    // 1) fused zero + pack (grid covers NPTS one-thread-per-point)
    zero_pack_kernel<<<NPTS / 256, 256>>>(x, out, n);

    // 2) condensation (one block per event)
    condense_kernel<<<NEV, 1024, dyn_smem>>>();

    // 3) scatter + splits
    const long long dout_elems = (long long)NPTS * NFEAT;
    const int do_splits = (n == dout_elems + NEV + 1) ? 1 : 0;
    scatter_splits_kernel<<<NEV, 512>>>(x, out, dout_elems, do_splits);
}